// round 7
// baseline (speedup 1.0000x reference)
#include <cuda_runtime.h>
#include <math.h>
#include <stdint.h>

// Problem constants
#define BSZ 128
#define PIX 196
#define EDIM 512
#define HDIM 512
#define ADIM 512
#define EMBD 512
#define VOC 32000
#define TT 20
#define ZROW 1536   // per-row layout: [ctx(512) | hn_slot0(512) | hn_slot1(512)]
#define G4 2048     // 4*H

// Split-GEMM geometry: K' = 3*512 = 1536, 192 k-steps of 8
#define KP 1536
#define NKS 192
#define NTILES (VOC / 8)        // 4000 n-tiles of 8

// ---------------- device scratch (no runtime allocation allowed) ----------------
__device__ float g_mean[BSZ * EDIM];
__device__ float g_h[BSZ * HDIM];
__device__ float g_c[BSZ * HDIM];
__device__ float g_z[BSZ * ZROW];                   // [ctx | hn0 | hn1] per row
__device__ float g_ka[BSZ * PIX * ADIM];            // 51.4 MB
__device__ float g_Wcat[G4 * KP];                   // repacked [j'=4h+gate][1536]
__device__ float g_bcat[G4];                        // b_lih+b_lhh, repacked
__device__ float g_scratch[(size_t)BSZ * TT * VOC]; // 327 MB, (b,t,v)
__device__ unsigned long long g_amax2[2][BSZ];      // double-buffered argmax keys
// mma-fragment-ordered operands for the tf32-split logits GEMM
__device__ float  g_Afrag[8 * NKS * 32 * 4];          // 786 KB  [mt][ks][lane][4]
__device__ float2 g_Bfrag[(size_t)NTILES * NKS * 32]; // 196.6 MB [nt][ks][lane]{b0,b1}

__device__ __forceinline__ float sigmf(float x) { return 1.0f / (1.0f + expf(-x)); }

__device__ __forceinline__ float tf32r(float x) {
    uint32_t u;
    asm("cvt.rna.tf32.f32 %0, %1;" : "=r"(u) : "f"(x));
    return __uint_as_float(u);
}

__device__ __forceinline__ unsigned long long amax_key(float v, int n) {
    unsigned u = __float_as_uint(v);
    u = (u & 0x80000000u) ? ~u : (u | 0x80000000u);
    return ((unsigned long long)u << 32) | (unsigned long long)(0xFFFFFFFFu - (unsigned)n);
}
__device__ __forceinline__ int amax_idx(unsigned long long key) {
    return (int)(0xFFFFFFFFu - (unsigned)(key & 0xFFFFFFFFull));
}

// A-fragment slot for logical A'[m][kp] (m16n8k8.row.col tf32 layout)
__device__ __forceinline__ void write_afrag(int m, int kp, float v) {
    const int mt = m >> 4, r = m & 15, g = r & 7, regM = r >> 3;
    const int ks = kp >> 3, t4 = kp & 3, regK = (kp >> 2) & 1;
    g_Afrag[(((mt * NKS + ks) * 32) + 4 * g + t4) * 4 + regK * 2 + regM] = v;
}

// ---------------- cp.async helpers ----------------
__device__ __forceinline__ uint32_t smem_u32(const void* p) {
    uint32_t a;
    asm("{ .reg .u64 t; cvta.to.shared.u64 t, %1; cvt.u32.u64 %0, t; }" : "=r"(a) : "l"(p));
    return a;
}
__device__ __forceinline__ void cp16(uint32_t s, const void* g) {
    asm volatile("cp.async.cg.shared.global [%0], [%1], 16;" :: "r"(s), "l"(g));
}
__device__ __forceinline__ void cp8(uint32_t s, const void* g) {
    asm volatile("cp.async.ca.shared.global [%0], [%1], 8;" :: "r"(s), "l"(g));
}
__device__ __forceinline__ void cp_commit() {
    asm volatile("cp.async.commit_group;" ::: "memory");
}
template <int N>
__device__ __forceinline__ void cp_wait() {
    asm volatile("cp.async.wait_group %0;" :: "n"(N) : "memory");
}

__device__ __forceinline__ void mma_tf32(float& c0, float& c1, float& c2, float& c3,
                                         uint32_t a0, uint32_t a1, uint32_t a2, uint32_t a3,
                                         uint32_t b0, uint32_t b1) {
    asm volatile(
        "mma.sync.aligned.m16n8k8.row.col.f32.tf32.tf32.f32 "
        "{%0,%1,%2,%3}, {%4,%5,%6,%7}, {%8,%9}, {%0,%1,%2,%3};"
        : "+f"(c0), "+f"(c1), "+f"(c2), "+f"(c3)
        : "r"(a0), "r"(a1), "r"(a2), "r"(a3), "r"(b0), "r"(b1));
}

// ================= tensor-core (mma.sync tf32) logits GEMM =================
#define L_STAGE_B 32768
#define L_NCHUNK 48          // 192 / 4
#define L_SMEM 69632         // 68 KB (>= 128*132*4 epilogue)

__global__ void __launch_bounds__(256, 2)
logits_mma(const float* __restrict__ bias, int t) {
    extern __shared__ char sm[];
    const uint32_t sb32 = smem_u32(sm);
    const int tid = threadIdx.x;
    const int wid = tid >> 5, lane = tid & 31;
    const int warpM = wid >> 2, warpN = wid & 3;   // 2 x 4 warp grid
    const int nb0 = blockIdx.x * 16;
    const int n0 = blockIdx.x * 128;

    float c[4][4][4];
#pragma unroll
    for (int mi = 0; mi < 4; mi++)
#pragma unroll
        for (int ni = 0; ni < 4; ni++)
#pragma unroll
            for (int r = 0; r < 4; r++) c[mi][ni][r] = 0.0f;

    auto load_stage = [&](int cc) {
        const int ks0 = cc * 4;
        const uint32_t base = sb32 + (cc & 1) * L_STAGE_B;
#pragma unroll
        for (int i = 0; i < 4; i++) {              // A: 1024 x 16B
            const int idx = tid + i * 256;
            const int mt = idx >> 7, rem = idx & 127;
            const int ksl = rem >> 5, ln = rem & 31;
            cp16(base + idx * 16,
                 g_Afrag + ((mt * NKS + ks0 + ksl) * 32 + ln) * 4);
        }
#pragma unroll
        for (int i = 0; i < 8; i++) {              // B: 2048 x 8B
            const int idx = tid + i * 256;
            const int ntl = idx >> 7;
            const int ksl = (idx >> 5) & 3, ln = idx & 31;
            cp8(base + 16384 + idx * 8,
                g_Bfrag + ((size_t)(nb0 + ntl) * NKS + ks0 + ksl) * 32 + ln);
        }
        cp_commit();
    };

    load_stage(0);
    for (int cc = 0; cc < L_NCHUNK; cc++) {
        if (cc + 1 < L_NCHUNK) { load_stage(cc + 1); cp_wait<1>(); }
        else                   { cp_wait<0>(); }
        __syncthreads();
        const char* buf = sm + (cc & 1) * L_STAGE_B;
#pragma unroll
        for (int ksl = 0; ksl < 4; ksl++) {
            uint4 af[4];
            uint2 bf[4];
#pragma unroll
            for (int mi = 0; mi < 4; mi++) {
                const int mt = warpM * 4 + mi;
                af[mi] = *(const uint4*)(buf + ((mt * 4 + ksl) * 32 + lane) * 16);
            }
#pragma unroll
            for (int ni = 0; ni < 4; ni++) {
                const int nt = warpN * 4 + ni;
                bf[ni] = *(const uint2*)(buf + 16384 + ((nt * 4 + ksl) * 32 + lane) * 8);
            }
#pragma unroll
            for (int mi = 0; mi < 4; mi++)
#pragma unroll
                for (int ni = 0; ni < 4; ni++)
                    mma_tf32(c[mi][ni][0], c[mi][ni][1], c[mi][ni][2], c[mi][ni][3],
                             af[mi].x, af[mi].y, af[mi].z, af[mi].w,
                             bf[ni].x, bf[ni].y);
        }
        __syncthreads();
    }

    // ---- epilogue ----
    float* st = (float*)sm;                         // 128 x 132
    const int g = lane >> 2, t4 = lane & 3;
#pragma unroll
    for (int mi = 0; mi < 4; mi++) {
        const int m = warpM * 64 + mi * 16 + g;
#pragma unroll
        for (int ni = 0; ni < 4; ni++) {
            const int col = warpN * 32 + ni * 8 + 2 * t4;
            st[m * 132 + col]           = c[mi][ni][0];
            st[m * 132 + col + 1]       = c[mi][ni][1];
            st[(m + 8) * 132 + col]     = c[mi][ni][2];
            st[(m + 8) * 132 + col + 1] = c[mi][ni][3];
        }
    }
    __syncthreads();

    {   // per-row argmax: 2 threads per row, 64 cols each
        const int row = tid & 127;
        const int c0 = (tid >> 7) * 64;
        float bestv = -3.4e38f;
        int bestn = 0;
#pragma unroll 8
        for (int cc2 = 0; cc2 < 64; cc2++) {
            const int col = c0 + cc2;
            float v = st[row * 132 + col] + __ldg(&bias[n0 + col]);
            if (v > bestv) { bestv = v; bestn = n0 + col; }
        }
        atomicMax(&g_amax2[t & 1][row], amax_key(bestv, bestn));
    }
    for (int idx = tid; idx < 128 * 128; idx += 256) {
        const int m2 = idx >> 7, cc2 = idx & 127;
        g_scratch[((size_t)m2 * TT + t) * VOC + n0 + cc2] =
            st[m2 * 132 + cc2] + __ldg(&bias[n0 + cc2]);
    }
}

// build B' fragments from W_out (once per launch)
__device__ __forceinline__ float wval(const float* __restrict__ W, int n, int kp) {
    if (kp < 512) return tf32r(W[(size_t)n * 512 + kp]);
    if (kp < 1024) {
        float x = W[(size_t)n * 512 + kp - 512];
        return tf32r(x - tf32r(x));
    }
    return tf32r(W[(size_t)n * 512 + kp - 1024]);
}
__global__ void k_bfrag(const float* __restrict__ W) {
    size_t i = (size_t)blockIdx.x * 256 + threadIdx.x;
    if (i >= (size_t)NTILES * NKS * 32) return;
    const int lane = (int)(i & 31);
    const size_t r = i >> 5;
    const int ks = (int)(r % NKS);
    const int nt = (int)(r / NKS);
    const int g = lane >> 2, t4 = lane & 3;
    const int n = nt * 8 + g;
    const int k1 = ks * 8 + t4;
    g_Bfrag[i] = make_float2(wval(W, n, k1), wval(W, n, k1 + 4));
}

// ================= big-tile fp32 SGEMM (ka only) ================
__global__ __launch_bounds__(256)
void sgemm_nt(const float* __restrict__ A, const float* __restrict__ B,
              const float* __restrict__ bias, float* __restrict__ C,
              int M, int N, int K) {
    __shared__ float As[8][128];
    __shared__ float Bs[8][128];
    const int bm = blockIdx.y * 128;
    const int bn = blockIdx.x * 128;
    const int tid = threadIdx.x;
    const int tx = tid & 15;
    const int ty = tid >> 4;
    const int lrow = tid >> 1;
    const int lcol = (tid & 1) << 2;

    const float* Ap = A + (size_t)(bm + lrow) * K + lcol;
    const float* Bp = B + (size_t)(bn + lrow) * K + lcol;

    float acc[8][8];
#pragma unroll
    for (int i = 0; i < 8; i++)
#pragma unroll
        for (int j = 0; j < 8; j++) acc[i][j] = 0.0f;

    for (int k0 = 0; k0 < K; k0 += 8) {
        float4 av = *reinterpret_cast<const float4*>(Ap + k0);
        float4 bv = *reinterpret_cast<const float4*>(Bp + k0);
        As[lcol + 0][lrow] = av.x; As[lcol + 1][lrow] = av.y;
        As[lcol + 2][lrow] = av.z; As[lcol + 3][lrow] = av.w;
        Bs[lcol + 0][lrow] = bv.x; Bs[lcol + 1][lrow] = bv.y;
        Bs[lcol + 2][lrow] = bv.z; Bs[lcol + 3][lrow] = bv.w;
        __syncthreads();
#pragma unroll
        for (int k = 0; k < 8; k++) {
            float4 a0 = *reinterpret_cast<const float4*>(&As[k][ty * 8]);
            float4 a1 = *reinterpret_cast<const float4*>(&As[k][ty * 8 + 4]);
            float4 b0 = *reinterpret_cast<const float4*>(&Bs[k][tx * 8]);
            float4 b1 = *reinterpret_cast<const float4*>(&Bs[k][tx * 8 + 4]);
            float am[8] = {a0.x, a0.y, a0.z, a0.w, a1.x, a1.y, a1.z, a1.w};
            float bb[8] = {b0.x, b0.y, b0.z, b0.w, b1.x, b1.y, b1.z, b1.w};
#pragma unroll
            for (int i = 0; i < 8; i++)
#pragma unroll
                for (int j = 0; j < 8; j++) acc[i][j] = fmaf(am[i], bb[j], acc[i][j]);
        }
        __syncthreads();
    }

    const int row0 = bm + ty * 8;
    const int col0 = bn + tx * 8;
#pragma unroll
    for (int i = 0; i < 8; i++) {
        const int mm = row0 + i;
#pragma unroll
        for (int j = 0; j < 8; j++) {
            const int n = col0 + j;
            C[(size_t)mm * N + n] = acc[i][j] + bias[n];
        }
    }
}

// ================= small-M GEMM (init only) =================
// MODE 0: C = acc + bias       (cn init)
// MODE 4: init hn: C + g_z hn slot 0 + A-fragment writes
template <int MODE>
__global__ __launch_bounds__(128)
void gemm_small(const float* __restrict__ A, const float* __restrict__ B,
                const float* __restrict__ bias, float* __restrict__ C,
                int M, int N, int K) {
    __shared__ float As[32][16];
    __shared__ float Bs[32][64];
    const int bn = blockIdx.x * 64;
    const int bm = blockIdx.y * 16;
    const int t = threadIdx.x;
    const int tx = t & 15;
    const int ty = t >> 4;
    const int ar = t >> 3;
    const int ac = (t & 7) * 4;
    const int br = t >> 1;
    const int bc = (t & 1) * 16;

    const float* Ap = A + (size_t)(bm + ar) * K + ac;
    const float* Bp = B + (size_t)(bn + br) * K + bc;

    float acc[2][4] = {};

    for (int k0 = 0; k0 < K; k0 += 32) {
        float4 av = *(const float4*)(Ap + k0);
        As[ac + 0][ar] = av.x; As[ac + 1][ar] = av.y;
        As[ac + 2][ar] = av.z; As[ac + 3][ar] = av.w;
        float4 b0 = *(const float4*)(Bp + k0);
        float4 b1 = *(const float4*)(Bp + k0 + 4);
        float4 b2 = *(const float4*)(Bp + k0 + 8);
        float4 b3 = *(const float4*)(Bp + k0 + 12);
        Bs[bc +  0][br] = b0.x; Bs[bc +  1][br] = b0.y;
        Bs[bc +  2][br] = b0.z; Bs[bc +  3][br] = b0.w;
        Bs[bc +  4][br] = b1.x; Bs[bc +  5][br] = b1.y;
        Bs[bc +  6][br] = b1.z; Bs[bc +  7][br] = b1.w;
        Bs[bc +  8][br] = b2.x; Bs[bc +  9][br] = b2.y;
        Bs[bc + 10][br] = b2.z; Bs[bc + 11][br] = b2.w;
        Bs[bc + 12][br] = b3.x; Bs[bc + 13][br] = b3.y;
        Bs[bc + 14][br] = b3.z; Bs[bc + 15][br] = b3.w;
        __syncthreads();
#pragma unroll
        for (int k = 0; k < 32; k++) {
            float a0 = As[k][2 * ty];
            float a1 = As[k][2 * ty + 1];
            float4 bv = *(const float4*)(&Bs[k][tx * 4]);
            acc[0][0] = fmaf(a0, bv.x, acc[0][0]);
            acc[0][1] = fmaf(a0, bv.y, acc[0][1]);
            acc[0][2] = fmaf(a0, bv.z, acc[0][2]);
            acc[0][3] = fmaf(a0, bv.w, acc[0][3]);
            acc[1][0] = fmaf(a1, bv.x, acc[1][0]);
            acc[1][1] = fmaf(a1, bv.y, acc[1][1]);
            acc[1][2] = fmaf(a1, bv.z, acc[1][2]);
            acc[1][3] = fmaf(a1, bv.w, acc[1][3]);
        }
        __syncthreads();
    }

    const int m0 = bm + 2 * ty;
    const int n0 = bn + 4 * tx;
#pragma unroll
    for (int r = 0; r < 2; r++) {
        const int m = m0 + r;
#pragma unroll
        for (int j = 0; j < 4; j++) {
            const int n = n0 + j;
            float v = acc[r][j] + bias[n];
            C[(size_t)m * N + n] = v;
            if (MODE == 4) {
                g_z[m * ZROW + 512 + n] = v;   // hn slot 0
                float hi = tf32r(v);
                float lo = tf32r(v - hi);
                write_afrag(m, n, hi);
                write_afrag(m, n + 512, hi);
                write_afrag(m, n + 1024, lo);
            }
        }
    }
}

// ================= fused front half: q + attention + gated ctx =================
// one block per batch row, 512 threads. q lives in smem (no global round trip).
__global__ __launch_bounds__(512)
void k_front(const float* __restrict__ feat,
             const float* __restrict__ W_oenc, const float* __restrict__ b_oenc,
             const float* __restrict__ Watt, const float* __restrict__ batt,
             const float* __restrict__ W_gate, const float* __restrict__ b_gate) {
    __shared__ __align__(16) float h_s[HDIM];
    __shared__ __align__(16) float q_s[ADIM];
    __shared__ __align__(16) float w_s[ADIM];
    __shared__ __align__(16) float ctx_s[EDIM];
    __shared__ float e_s[PIX];
    __shared__ float red[16];
    const int b = blockIdx.x, tid = threadIdx.x;
    const int warp = tid >> 5, lane = tid & 31;

    h_s[tid] = g_h[b * HDIM + tid];
    w_s[tid] = Watt[tid];
    __syncthreads();

    // ---- phase 1: q[a] = dot(hn, W_oenc[a,:]) + b_oenc[a] ----
    {
        const float4* r4 = (const float4*)(W_oenc + (size_t)tid * HDIM);
        const float4* s4 = (const float4*)h_s;
        float a0 = 0, a1 = 0, a2 = 0, a3 = 0;
#pragma unroll 8
        for (int k = 0; k < 128; k += 4) {
            float4 w0 = __ldg(&r4[k]),     w1 = __ldg(&r4[k + 1]);
            float4 w2 = __ldg(&r4[k + 2]), w3 = __ldg(&r4[k + 3]);
            float4 h0 = s4[k], h1 = s4[k + 1], h2 = s4[k + 2], h3 = s4[k + 3];
            a0 = fmaf(w0.x, h0.x, fmaf(w0.y, h0.y, fmaf(w0.z, h0.z, fmaf(w0.w, h0.w, a0))));
            a1 = fmaf(w1.x, h1.x, fmaf(w1.y, h1.y, fmaf(w1.z, h1.z, fmaf(w1.w, h1.w, a1))));
            a2 = fmaf(w2.x, h2.x, fmaf(w2.y, h2.y, fmaf(w2.z, h2.z, fmaf(w2.w, h2.w, a2))));
            a3 = fmaf(w3.x, h3.x, fmaf(w3.y, h3.y, fmaf(w3.z, h3.z, fmaf(w3.w, h3.w, a3))));
        }
        q_s[tid] = (a0 + a1) + (a2 + a3) + __ldg(&b_oenc[tid]);
    }
    __syncthreads();

    // ---- phase 2: scores e[p] = relu(ka + q) . W_att + b_att ----
    for (int p = warp; p < PIX; p += 16) {
        const float* kap = g_ka + ((size_t)(b * PIX + p)) * ADIM;
        float s = 0.0f;
        for (int a = lane; a < ADIM; a += 32) {
            float v = kap[a] + q_s[a];
            s += fmaxf(v, 0.0f) * w_s[a];
        }
#pragma unroll
        for (int o = 16; o; o >>= 1) s += __shfl_xor_sync(0xffffffffu, s, o);
        if (lane == 0) e_s[p] = s + batt[0];
    }
    __syncthreads();

    // ---- softmax over 196 ----
    float m = (tid < PIX) ? e_s[tid] : -3.4e38f;
#pragma unroll
    for (int o = 16; o; o >>= 1) m = fmaxf(m, __shfl_xor_sync(0xffffffffu, m, o));
    if (lane == 0) red[warp] = m;
    __syncthreads();
    if (tid == 0) {
        float v = red[0];
        for (int i = 1; i < 16; i++) v = fmaxf(v, red[i]);
        red[0] = v;
    }
    __syncthreads();
    m = red[0];
    float ex = (tid < PIX) ? expf(e_s[tid] - m) : 0.0f;
    float ssum = ex;
#pragma unroll
    for (int o = 16; o; o >>= 1) ssum += __shfl_xor_sync(0xffffffffu, ssum, o);
    __syncthreads();
    if (lane == 0) red[warp] = ssum;
    __syncthreads();
    if (tid == 0) {
        float v = 0.0f;
        for (int i = 0; i < 16; i++) v += red[i];
        red[0] = 1.0f / v;
    }
    __syncthreads();
    if (tid < PIX) e_s[tid] = ex * red[0];
    __syncthreads();

    // ---- ctx[e] = sum_p alpha[p] * feature[b,p,e] ----
    {
        float acc = 0.0f;
        const float* fb = feat + (size_t)b * PIX * EDIM + tid;
        for (int p = 0; p < PIX; p++) acc = fmaf(e_s[p], fb[(size_t)p * EDIM], acc);
        ctx_s[tid] = acc;
    }
    __syncthreads();

    // ---- phase 3: gated ctx -> g_z[:, 0:512] ----
    {
        const float4* r4 = (const float4*)(W_gate + (size_t)tid * EDIM);
        const float4* s4 = (const float4*)ctx_s;
        float a0 = 0, a1 = 0, a2 = 0, a3 = 0;
#pragma unroll 8
        for (int k = 0; k < 128; k += 4) {
            float4 w0 = __ldg(&r4[k]),     w1 = __ldg(&r4[k + 1]);
            float4 w2 = __ldg(&r4[k + 2]), w3 = __ldg(&r4[k + 3]);
            float4 h0 = s4[k], h1 = s4[k + 1], h2 = s4[k + 2], h3 = s4[k + 3];
            a0 = fmaf(w0.x, h0.x, fmaf(w0.y, h0.y, fmaf(w0.z, h0.z, fmaf(w0.w, h0.w, a0))));
            a1 = fmaf(w1.x, h1.x, fmaf(w1.y, h1.y, fmaf(w1.z, h1.z, fmaf(w1.w, h1.w, a1))));
            a2 = fmaf(w2.x, h2.x, fmaf(w2.y, h2.y, fmaf(w2.z, h2.z, fmaf(w2.w, h2.w, a2))));
            a3 = fmaf(w3.x, h3.x, fmaf(w3.y, h3.y, fmaf(w3.z, h3.z, fmaf(w3.w, h3.w, a3))));
        }
        float s = sigmf((a0 + a1) + (a2 + a3) + __ldg(&b_gate[tid]));
        g_z[b * ZROW + tid] = s * ctx_s[tid];
    }
}

// ================= fused gates GEMM + LSTM cell =================
// C' cols j' = 4h + gate; epilogue = LSTM cell. hn slot ping-pong breaks the
// R6 intra-kernel race: reads hn slot rd_par, writes hn slot wr_par (!= rd_par).
// A row m = [emb[tok_m](512) | ctx(512) | hn_rd(512)], K = 1536.
__global__ __launch_bounds__(128)
void k_gates_cell(const float* __restrict__ emb,
                  const unsigned long long* __restrict__ am_rd,
                  unsigned long long* __restrict__ am_clr,
                  int rd_par, int wr_par) {
    __shared__ float As[2][32][16];
    __shared__ float Bs[2][32][64];
    const int bn = blockIdx.x * 64;
    const int bm = blockIdx.y * 16;
    const int t = threadIdx.x;
    const int tx = t & 15;
    const int ty = t >> 4;
    const int ar = t >> 3;
    const int ac = (t & 7) * 4;
    const int br = t >> 1;
    const int bc = (t & 1) * 16;
    const int arow = bm + ar;

    const size_t tokoff = (size_t)amax_idx(am_rd[arow]) * EMBD;
    const float* Bp = g_Wcat + (size_t)(bn + br) * KP + bc;
    const int hn_rd = 512 + rd_par * 512;

    auto ldA4 = [&](int k0) -> float4 {
        const int kk = k0 + ac;
        const float* s;
        if (kk < 512)       s = emb + tokoff + kk;
        else if (kk < 1024) s = g_z + (size_t)arow * ZROW + (kk - 512);       // ctx
        else                s = g_z + (size_t)arow * ZROW + hn_rd + (kk - 1024); // hn
        return *(const float4*)s;
    };

    float4 av = ldA4(0);
    float4 bv0 = *(const float4*)(Bp + 0);
    float4 bv1 = *(const float4*)(Bp + 4);
    float4 bv2 = *(const float4*)(Bp + 8);
    float4 bv3 = *(const float4*)(Bp + 12);

    float acc[2][4] = {};
    const int nk = KP >> 5;   // 48
    for (int it = 0; it < nk; it++) {
        const int st = it & 1;
        As[st][ac + 0][ar] = av.x; As[st][ac + 1][ar] = av.y;
        As[st][ac + 2][ar] = av.z; As[st][ac + 3][ar] = av.w;
        Bs[st][bc +  0][br] = bv0.x; Bs[st][bc +  1][br] = bv0.y;
        Bs[st][bc +  2][br] = bv0.z; Bs[st][bc +  3][br] = bv0.w;
        Bs[st][bc +  4][br] = bv1.x; Bs[st][bc +  5][br] = bv1.y;
        Bs[st][bc +  6][br] = bv1.z; Bs[st][bc +  7][br] = bv1.w;
        Bs[st][bc +  8][br] = bv2.x; Bs[st][bc +  9][br] = bv2.y;
        Bs[st][bc + 10][br] = bv2.z; Bs[st][bc + 11][br] = bv2.w;
        Bs[st][bc + 12][br] = bv3.x; Bs[st][bc + 13][br] = bv3.y;
        Bs[st][bc + 14][br] = bv3.z; Bs[st][bc + 15][br] = bv3.w;
        __syncthreads();
        if (it + 1 < nk) {
            const int k0 = (it + 1) << 5;
            av = ldA4(k0);
            bv0 = *(const float4*)(Bp + k0);
            bv1 = *(const float4*)(Bp + k0 + 4);
            bv2 = *(const float4*)(Bp + k0 + 8);
            bv3 = *(const float4*)(Bp + k0 + 12);
        }
#pragma unroll
        for (int k = 0; k < 32; k++) {
            float a0 = As[st][k][2 * ty];
            float a1 = As[st][k][2 * ty + 1];
            float4 bv = *(const float4*)(&Bs[st][k][tx * 4]);
            acc[0][0] = fmaf(a0, bv.x, acc[0][0]);
            acc[0][1] = fmaf(a0, bv.y, acc[0][1]);
            acc[0][2] = fmaf(a0, bv.z, acc[0][2]);
            acc[0][3] = fmaf(a0, bv.w, acc[0][3]);
            acc[1][0] = fmaf(a1, bv.x, acc[1][0]);
            acc[1][1] = fmaf(a1, bv.y, acc[1][1]);
            acc[1][2] = fmaf(a1, bv.z, acc[1][2]);
            acc[1][3] = fmaf(a1, bv.w, acc[1][3]);
        }
        __syncthreads();
    }

    // ---- fused cell epilogue (writes hn slot wr_par: no reader in this launch) ----
    const int m0 = bm + 2 * ty;
    const int n0 = bn + 4 * tx;       // j' of gate 0
    const int h = n0 >> 2;
#pragma unroll
    for (int r = 0; r < 2; r++) {
        const int m = m0 + r;
        float gi = acc[r][0] + g_bcat[n0];
        float gf = acc[r][1] + g_bcat[n0 + 1];
        float gg = acc[r][2] + g_bcat[n0 + 2];
        float go = acc[r][3] + g_bcat[n0 + 3];
        float c = sigmf(gf) * g_c[m * HDIM + h] + sigmf(gi) * tanhf(gg);
        float hn = sigmf(go) * tanhf(c);
        g_c[m * HDIM + h] = c;
        g_h[m * HDIM + h] = hn;
        g_z[m * ZROW + 512 + wr_par * 512 + h] = hn;
        float hi = tf32r(hn);
        float lo = tf32r(hn - hi);
        write_afrag(m, h, hi);
        write_afrag(m, h + 512, hi);
        write_afrag(m, h + 1024, lo);
        if (blockIdx.x == 0 && tx == 0) am_clr[m] = 0ull;
    }
}

// ---------------- small kernels ----------------
__global__ void k_mean(const float* __restrict__ feat) {
    int b = blockIdx.x, e = threadIdx.x;
    const float* f = feat + (size_t)b * PIX * EDIM + e;
    float s = 0.0f;
    for (int p = 0; p < PIX; p++) s += f[(size_t)p * EDIM];
    g_mean[b * EDIM + e] = s * (1.0f / (float)PIX);
}

// seed buffer 1 with the first caption token (gates_0 reads buffer (0+1)&1 = 1)
__global__ void k_x0(const int* __restrict__ captions) {
    int b = threadIdx.x;   // 128 threads, 1 block
    g_amax2[1][b] = amax_key(0.0f, captions[b * TT]);
}

// repack [W_lih|W_lhh] so output row j' = 4h + gate; combined bias too
__global__ void k_pack(const float* __restrict__ Wlih, const float* __restrict__ Wlhh,
                       const float* __restrict__ blih, const float* __restrict__ blhh) {
    int i = blockIdx.x * blockDim.x + threadIdx.x;
    if (i >= G4 * KP) return;
    int jp = i / KP, k = i - jp * KP;
    int h = jp >> 2, gate = jp & 3;
    int orig = gate * 512 + h;
    g_Wcat[i] = (k < 1024) ? Wlih[(size_t)orig * 1024 + k]
                           : Wlhh[(size_t)orig * 512 + (k - 1024)];
    if (k == 0) g_bcat[jp] = blih[orig] + blhh[orig];
}

// final transpose: scratch (b,t,v) -> out (b,v,t)
__global__ __launch_bounds__(256)
void k_tr(float* __restrict__ out) {
    __shared__ float sm[256 * 21];
    const int b = blockIdx.y;
    const int v0 = blockIdx.x * 256;
    const int tid = threadIdx.x;
    const float* src = g_scratch + (size_t)b * TT * VOC;
#pragma unroll
    for (int t = 0; t < TT; t++) sm[tid * 21 + t] = src[(size_t)t * VOC + v0 + tid];
    __syncthreads();
    float* ob = out + (size_t)b * VOC * TT + (size_t)v0 * TT;
    for (int e = tid; e < 256 * TT; e += 256) {
        int v = e / TT, t = e - v * TT;
        ob[e] = sm[v * 21 + t];
    }
}

// ---------------- host launch ----------------
static inline void* sym_addr(const void* symbol) {
    void* p = nullptr;
    cudaGetSymbolAddress(&p, symbol);
    return p;
}

extern "C" void kernel_launch(void* const* d_in, const int* in_sizes, int n_in,
                              void* d_out, int out_size) {
    const float* feat    = (const float*)d_in[0];
    const int*   caps    = (const int*)d_in[1];
    const float* W_ienc  = (const float*)d_in[2];
    const float* b_ienc  = (const float*)d_in[3];
    const float* W_oenc  = (const float*)d_in[4];
    const float* b_oenc  = (const float*)d_in[5];
    const float* W_att   = (const float*)d_in[6];
    const float* b_att   = (const float*)d_in[7];
    const float* W_inith = (const float*)d_in[8];
    const float* b_inith = (const float*)d_in[9];
    const float* W_initc = (const float*)d_in[10];
    const float* b_initc = (const float*)d_in[11];
    const float* W_gate  = (const float*)d_in[12];
    const float* b_gate  = (const float*)d_in[13];
    const float* embT    = (const float*)d_in[14];
    const float* W_lih   = (const float*)d_in[15];
    const float* W_lhh   = (const float*)d_in[16];
    const float* b_lih   = (const float*)d_in[17];
    const float* b_lhh   = (const float*)d_in[18];
    const float* W_out   = (const float*)d_in[19];
    const float* b_out   = (const float*)d_in[20];
    float* out = (float*)d_out;

    float* p_mean = (float*)sym_addr(g_mean);
    float* p_h    = (float*)sym_addr(g_h);
    float* p_c    = (float*)sym_addr(g_c);
    float* p_ka   = (float*)sym_addr(g_ka);
    unsigned long long* p_am = (unsigned long long*)sym_addr(g_amax2);  // [2][BSZ]

    static cudaStream_t s1 = nullptr;
    static cudaEvent_t evRoot, evK, evB;
    if (!s1) {
        cudaFuncSetAttribute(logits_mma, cudaFuncAttributeMaxDynamicSharedMemorySize, L_SMEM);
        cudaStreamCreateWithFlags(&s1, cudaStreamNonBlocking);
        cudaEventCreateWithFlags(&evRoot, cudaEventDisableTiming);
        cudaEventCreateWithFlags(&evK,    cudaEventDisableTiming);
        cudaEventCreateWithFlags(&evB,    cudaEventDisableTiming);
    }

    // ---- fork side stream: ka GEMM + B-fragment build ----
    cudaEventRecord(evRoot, 0);
    cudaStreamWaitEvent(s1, evRoot, 0);
    sgemm_nt<<<dim3(ADIM / 128, (BSZ * PIX) / 128), 256, 0, s1>>>(
        feat, W_ienc, b_ienc, p_ka, BSZ * PIX, ADIM, EDIM);
    cudaEventRecord(evK, s1);
    {
        size_t nB = (size_t)NTILES * NKS * 32;
        k_bfrag<<<(unsigned)((nB + 255) / 256), 256, 0, s1>>>(W_out);
    }
    cudaEventRecord(evB, s1);

    // ---- main-stream setup ----
    k_mean<<<BSZ, 512>>>(feat);
    gemm_small<4><<<dim3(HDIM / 64, BSZ / 16), 128>>>(p_mean, W_inith, b_inith, p_h,
                                                      BSZ, HDIM, EDIM);
    gemm_small<0><<<dim3(HDIM / 64, BSZ / 16), 128>>>(p_mean, W_initc, b_initc, p_c,
                                                      BSZ, HDIM, EDIM);
    k_x0<<<1, 128>>>(caps);
    k_pack<<<(G4 * KP + 255) / 256, 256>>>(W_lih, W_lhh, b_lih, b_lhh);

    cudaStreamWaitEvent(0, evK, 0);   // front needs ka
    cudaStreamWaitEvent(0, evB, 0);   // logits needs Bfrag; also rejoins s1

    // ---- T recurrent steps (single stream, 3 kernels each) ----
    for (int t = 0; t < TT; t++) {
        k_front<<<BSZ, 512>>>(feat, W_oenc, b_oenc, W_att, b_att, W_gate, b_gate);
        k_gates_cell<<<dim3(G4 / 64, BSZ / 16), 128>>>(
            embT, p_am + ((t + 1) & 1) * BSZ, p_am + (t & 1) * BSZ,
            t & 1, (t + 1) & 1);
        logits_mma<<<VOC / 128, 256, L_SMEM>>>(b_out, t);
    }

    k_tr<<<dim3(VOC / 256, BSZ), 256>>>(out);
}

// round 8
// speedup vs baseline: 1.1897x; 1.1897x over previous
#include <cuda_runtime.h>
#include <math.h>
#include <stdint.h>

// Problem constants
#define BSZ 128
#define PIX 196
#define EDIM 512
#define HDIM 512
#define ADIM 512
#define EMBD 512
#define VOC 32000
#define TT 20
#define ZROW 1536   // per-row: [ctx(512) | hn_slot0(512) | hn_slot1(512)]
#define G4 2048     // 4*H

// Split-GEMM geometry: K' = 3*512 = 1536, 192 k-steps of 8
#define KP 1536
#define NKS 192
#define NTILES (VOC / 8)        // 4000 n-tiles of 8

// ---------------- device scratch ----------------
__device__ float g_mean[BSZ * EDIM];
__device__ float g_h[BSZ * HDIM];
__device__ float g_c[BSZ * HDIM];
__device__ float g_q[BSZ * ADIM];
__device__ float g_ctx[BSZ * EDIM];
__device__ float g_z[BSZ * ZROW];                   // [ctx | hn0 | hn1]
__device__ float g_ka[BSZ * PIX * ADIM];            // 51.4 MB
__device__ float g_Wcat[G4 * KP];                   // repacked [j'=4h+gate][1536]
__device__ float g_bcat[G4];
__device__ float g_scratch[(size_t)BSZ * TT * VOC]; // 327 MB, (b,t,v)
__device__ unsigned long long g_amax2[2][BSZ];      // double-buffered argmax keys
__device__ float  g_Afrag[8 * NKS * 32 * 4];          // 786 KB
__device__ float2 g_Bfrag[(size_t)NTILES * NKS * 32]; // 196.6 MB

__device__ __forceinline__ float sigmf(float x) { return 1.0f / (1.0f + expf(-x)); }

__device__ __forceinline__ float tf32r(float x) {
    uint32_t u;
    asm("cvt.rna.tf32.f32 %0, %1;" : "=r"(u) : "f"(x));
    return __uint_as_float(u);
}

__device__ __forceinline__ unsigned long long amax_key(float v, int n) {
    unsigned u = __float_as_uint(v);
    u = (u & 0x80000000u) ? ~u : (u | 0x80000000u);
    return ((unsigned long long)u << 32) | (unsigned long long)(0xFFFFFFFFu - (unsigned)n);
}
__device__ __forceinline__ int amax_idx(unsigned long long key) {
    return (int)(0xFFFFFFFFu - (unsigned)(key & 0xFFFFFFFFull));
}

__device__ __forceinline__ void write_afrag(int m, int kp, float v) {
    const int mt = m >> 4, r = m & 15, g = r & 7, regM = r >> 3;
    const int ks = kp >> 3, t4 = kp & 3, regK = (kp >> 2) & 1;
    g_Afrag[(((mt * NKS + ks) * 32) + 4 * g + t4) * 4 + regK * 2 + regM] = v;
}

// ---------------- cp.async / mma helpers ----------------
__device__ __forceinline__ uint32_t smem_u32(const void* p) {
    uint32_t a;
    asm("{ .reg .u64 t; cvta.to.shared.u64 t, %1; cvt.u32.u64 %0, t; }" : "=r"(a) : "l"(p));
    return a;
}
__device__ __forceinline__ void cp16(uint32_t s, const void* g) {
    asm volatile("cp.async.cg.shared.global [%0], [%1], 16;" :: "r"(s), "l"(g));
}
__device__ __forceinline__ void cp8(uint32_t s, const void* g) {
    asm volatile("cp.async.ca.shared.global [%0], [%1], 8;" :: "r"(s), "l"(g));
}
__device__ __forceinline__ void cp_commit() {
    asm volatile("cp.async.commit_group;" ::: "memory");
}
template <int N>
__device__ __forceinline__ void cp_wait() {
    asm volatile("cp.async.wait_group %0;" :: "n"(N) : "memory");
}

__device__ __forceinline__ void mma_tf32(float& c0, float& c1, float& c2, float& c3,
                                         uint32_t a0, uint32_t a1, uint32_t a2, uint32_t a3,
                                         uint32_t b0, uint32_t b1) {
    asm volatile(
        "mma.sync.aligned.m16n8k8.row.col.f32.tf32.tf32.f32 "
        "{%0,%1,%2,%3}, {%4,%5,%6,%7}, {%8,%9}, {%0,%1,%2,%3};"
        : "+f"(c0), "+f"(c1), "+f"(c2), "+f"(c3)
        : "r"(a0), "r"(a1), "r"(a2), "r"(a3), "r"(b0), "r"(b1));
}

// ================= tensor-core (mma.sync tf32) logits GEMM =================
#define L_STAGE_B 32768
#define L_NCHUNK 48
#define L_SMEM 69632

__global__ void __launch_bounds__(256, 2)
logits_mma(const float* __restrict__ bias, int t) {
    extern __shared__ char sm[];
    const uint32_t sb32 = smem_u32(sm);
    const int tid = threadIdx.x;
    const int wid = tid >> 5, lane = tid & 31;
    const int warpM = wid >> 2, warpN = wid & 3;
    const int nb0 = blockIdx.x * 16;
    const int n0 = blockIdx.x * 128;

    float c[4][4][4];
#pragma unroll
    for (int mi = 0; mi < 4; mi++)
#pragma unroll
        for (int ni = 0; ni < 4; ni++)
#pragma unroll
            for (int r = 0; r < 4; r++) c[mi][ni][r] = 0.0f;

    auto load_stage = [&](int cc) {
        const int ks0 = cc * 4;
        const uint32_t base = sb32 + (cc & 1) * L_STAGE_B;
#pragma unroll
        for (int i = 0; i < 4; i++) {
            const int idx = tid + i * 256;
            const int mt = idx >> 7, rem = idx & 127;
            const int ksl = rem >> 5, ln = rem & 31;
            cp16(base + idx * 16,
                 g_Afrag + ((mt * NKS + ks0 + ksl) * 32 + ln) * 4);
        }
#pragma unroll
        for (int i = 0; i < 8; i++) {
            const int idx = tid + i * 256;
            const int ntl = idx >> 7;
            const int ksl = (idx >> 5) & 3, ln = idx & 31;
            cp8(base + 16384 + idx * 8,
                g_Bfrag + ((size_t)(nb0 + ntl) * NKS + ks0 + ksl) * 32 + ln);
        }
        cp_commit();
    };

    load_stage(0);
    for (int cc = 0; cc < L_NCHUNK; cc++) {
        if (cc + 1 < L_NCHUNK) { load_stage(cc + 1); cp_wait<1>(); }
        else                   { cp_wait<0>(); }
        __syncthreads();
        const char* buf = sm + (cc & 1) * L_STAGE_B;
#pragma unroll
        for (int ksl = 0; ksl < 4; ksl++) {
            uint4 af[4];
            uint2 bf[4];
#pragma unroll
            for (int mi = 0; mi < 4; mi++) {
                const int mt = warpM * 4 + mi;
                af[mi] = *(const uint4*)(buf + ((mt * 4 + ksl) * 32 + lane) * 16);
            }
#pragma unroll
            for (int ni = 0; ni < 4; ni++) {
                const int nt = warpN * 4 + ni;
                bf[ni] = *(const uint2*)(buf + 16384 + ((nt * 4 + ksl) * 32 + lane) * 8);
            }
#pragma unroll
            for (int mi = 0; mi < 4; mi++)
#pragma unroll
                for (int ni = 0; ni < 4; ni++)
                    mma_tf32(c[mi][ni][0], c[mi][ni][1], c[mi][ni][2], c[mi][ni][3],
                             af[mi].x, af[mi].y, af[mi].z, af[mi].w,
                             bf[ni].x, bf[ni].y);
        }
        __syncthreads();
    }

    // ---- epilogue ----
    float* st = (float*)sm;                         // 128 x 132
    const int g = lane >> 2, t4 = lane & 3;
#pragma unroll
    for (int mi = 0; mi < 4; mi++) {
        const int m = warpM * 64 + mi * 16 + g;
#pragma unroll
        for (int ni = 0; ni < 4; ni++) {
            const int col = warpN * 32 + ni * 8 + 2 * t4;
            st[m * 132 + col]           = c[mi][ni][0];
            st[m * 132 + col + 1]       = c[mi][ni][1];
            st[(m + 8) * 132 + col]     = c[mi][ni][2];
            st[(m + 8) * 132 + col + 1] = c[mi][ni][3];
        }
    }
    __syncthreads();

    {
        const int row = tid & 127;
        const int c0 = (tid >> 7) * 64;
        float bestv = -3.4e38f;
        int bestn = 0;
#pragma unroll 8
        for (int cc2 = 0; cc2 < 64; cc2++) {
            const int col = c0 + cc2;
            float v = st[row * 132 + col] + __ldg(&bias[n0 + col]);
            if (v > bestv) { bestv = v; bestn = n0 + col; }
        }
        atomicMax(&g_amax2[t & 1][row], amax_key(bestv, bestn));
    }
    for (int idx = tid; idx < 128 * 128; idx += 256) {
        const int m2 = idx >> 7, cc2 = idx & 127;
        g_scratch[((size_t)m2 * TT + t) * VOC + n0 + cc2] =
            st[m2 * 132 + cc2] + __ldg(&bias[n0 + cc2]);
    }
}

// build B' fragments from W_out (once per launch)
__device__ __forceinline__ float wval(const float* __restrict__ W, int n, int kp) {
    if (kp < 512) return tf32r(W[(size_t)n * 512 + kp]);
    if (kp < 1024) {
        float x = W[(size_t)n * 512 + kp - 512];
        return tf32r(x - tf32r(x));
    }
    return tf32r(W[(size_t)n * 512 + kp - 1024]);
}
__global__ void k_bfrag(const float* __restrict__ W) {
    size_t i = (size_t)blockIdx.x * 256 + threadIdx.x;
    if (i >= (size_t)NTILES * NKS * 32) return;
    const int lane = (int)(i & 31);
    const size_t r = i >> 5;
    const int ks = (int)(r % NKS);
    const int nt = (int)(r / NKS);
    const int g = lane >> 2, t4 = lane & 3;
    const int n = nt * 8 + g;
    const int k1 = ks * 8 + t4;
    g_Bfrag[i] = make_float2(wval(W, n, k1), wval(W, n, k1 + 4));
}

// ================= big-tile fp32 SGEMM (ka only) ================
__global__ __launch_bounds__(256)
void sgemm_nt(const float* __restrict__ A, const float* __restrict__ B,
              const float* __restrict__ bias, float* __restrict__ C,
              int M, int N, int K) {
    __shared__ float As[8][128];
    __shared__ float Bs[8][128];
    const int bm = blockIdx.y * 128;
    const int bn = blockIdx.x * 128;
    const int tid = threadIdx.x;
    const int tx = tid & 15;
    const int ty = tid >> 4;
    const int lrow = tid >> 1;
    const int lcol = (tid & 1) << 2;

    const float* Ap = A + (size_t)(bm + lrow) * K + lcol;
    const float* Bp = B + (size_t)(bn + lrow) * K + lcol;

    float acc[8][8];
#pragma unroll
    for (int i = 0; i < 8; i++)
#pragma unroll
        for (int j = 0; j < 8; j++) acc[i][j] = 0.0f;

    for (int k0 = 0; k0 < K; k0 += 8) {
        float4 av = *reinterpret_cast<const float4*>(Ap + k0);
        float4 bv = *reinterpret_cast<const float4*>(Bp + k0);
        As[lcol + 0][lrow] = av.x; As[lcol + 1][lrow] = av.y;
        As[lcol + 2][lrow] = av.z; As[lcol + 3][lrow] = av.w;
        Bs[lcol + 0][lrow] = bv.x; Bs[lcol + 1][lrow] = bv.y;
        Bs[lcol + 2][lrow] = bv.z; Bs[lcol + 3][lrow] = bv.w;
        __syncthreads();
#pragma unroll
        for (int k = 0; k < 8; k++) {
            float4 a0 = *reinterpret_cast<const float4*>(&As[k][ty * 8]);
            float4 a1 = *reinterpret_cast<const float4*>(&As[k][ty * 8 + 4]);
            float4 b0 = *reinterpret_cast<const float4*>(&Bs[k][tx * 8]);
            float4 b1 = *reinterpret_cast<const float4*>(&Bs[k][tx * 8 + 4]);
            float am[8] = {a0.x, a0.y, a0.z, a0.w, a1.x, a1.y, a1.z, a1.w};
            float bb[8] = {b0.x, b0.y, b0.z, b0.w, b1.x, b1.y, b1.z, b1.w};
#pragma unroll
            for (int i = 0; i < 8; i++)
#pragma unroll
                for (int j = 0; j < 8; j++) acc[i][j] = fmaf(am[i], bb[j], acc[i][j]);
        }
        __syncthreads();
    }

    const int row0 = bm + ty * 8;
    const int col0 = bn + tx * 8;
#pragma unroll
    for (int i = 0; i < 8; i++) {
        const int mm = row0 + i;
#pragma unroll
        for (int j = 0; j < 8; j++) {
            const int n = col0 + j;
            C[(size_t)mm * N + n] = acc[i][j] + bias[n];
        }
    }
}

// ================= K-split small-M GEMM (256 threads, 2 K-groups) =================
// C[128,N] = A[128,K]*B[N,K]^T. Each 128-thread group handles K/2 with BM=16,
// BN=64, BK=32 tiles + depth-1 register prefetch; smem reduction at the end.
// Halves the serial DRAM-latency chain that bounded the 128-thread version.
// MODE 0: C = acc + bias                       (q, cn-init)
// MODE 1: g_z[m][n] = sigmoid(acc+bias)*g_ctx  (gated ctx)
// MODE 2: gates + fused LSTM cell (+emb gather, hn ping-pong, amax clear)
// MODE 4: init hn: C + g_z hn slot 0 + A-fragment writes
template <int MODE>
__global__ __launch_bounds__(256)
void gemm_ks(const float* __restrict__ A, const float* __restrict__ B,
             const float* __restrict__ bias, float* __restrict__ C,
             int N, int K,
             const float* __restrict__ emb,
             const unsigned long long* __restrict__ am_rd,
             unsigned long long* __restrict__ am_clr,
             int rd_par, int wr_par) {
    __shared__ float As[2][2][32][16];
    __shared__ float Bs[2][2][32][64];
    __shared__ float red[128][8];
    const int bn = blockIdx.x * 64;
    const int bm = blockIdx.y * 16;
    const int tid = threadIdx.x;
    const int l = tid & 127;
    const int g = tid >> 7;               // K-group
    const int tx = l & 15;
    const int ty = l >> 4;
    const int ar = l >> 3;
    const int ac = (l & 7) * 4;
    const int br = l >> 1;
    const int bc = (l & 1) * 16;
    const int arow = bm + ar;
    const int kbase = g * (K >> 1);

    size_t tokoff = 0;
    if (MODE == 2) tokoff = (size_t)amax_idx(am_rd[arow]) * EMBD;
    const int hn_rd = 512 + rd_par * 512;

    const float* Bp = B + (size_t)(bn + br) * K + kbase + bc;

    auto ldA4 = [&](int k0) -> float4 {
        const int kk = kbase + k0 + ac;
        if (MODE == 2) {
            const float* s;
            if (kk < 512)       s = emb + tokoff + kk;
            else if (kk < 1024) s = g_z + (size_t)arow * ZROW + (kk - 512);      // ctx
            else                s = g_z + (size_t)arow * ZROW + hn_rd + (kk - 1024);
            return *(const float4*)s;
        }
        return *(const float4*)(A + (size_t)arow * K + kk);
    };

    float4 av = ldA4(0);
    float4 bv0 = *(const float4*)(Bp + 0);
    float4 bv1 = *(const float4*)(Bp + 4);
    float4 bv2 = *(const float4*)(Bp + 8);
    float4 bv3 = *(const float4*)(Bp + 12);

    float acc[2][4] = {};
    const int nk = K >> 6;                 // (K/2)/32
    for (int it = 0; it < nk; it++) {
        const int st = it & 1;
        As[g][st][ac + 0][ar] = av.x; As[g][st][ac + 1][ar] = av.y;
        As[g][st][ac + 2][ar] = av.z; As[g][st][ac + 3][ar] = av.w;
        Bs[g][st][bc +  0][br] = bv0.x; Bs[g][st][bc +  1][br] = bv0.y;
        Bs[g][st][bc +  2][br] = bv0.z; Bs[g][st][bc +  3][br] = bv0.w;
        Bs[g][st][bc +  4][br] = bv1.x; Bs[g][st][bc +  5][br] = bv1.y;
        Bs[g][st][bc +  6][br] = bv1.z; Bs[g][st][bc +  7][br] = bv1.w;
        Bs[g][st][bc +  8][br] = bv2.x; Bs[g][st][bc +  9][br] = bv2.y;
        Bs[g][st][bc + 10][br] = bv2.z; Bs[g][st][bc + 11][br] = bv2.w;
        Bs[g][st][bc + 12][br] = bv3.x; Bs[g][st][bc + 13][br] = bv3.y;
        Bs[g][st][bc + 14][br] = bv3.z; Bs[g][st][bc + 15][br] = bv3.w;
        __syncthreads();
        if (it + 1 < nk) {                 // prefetch next tile during compute
            const int k0 = (it + 1) << 5;
            av = ldA4(k0);
            bv0 = *(const float4*)(Bp + k0);
            bv1 = *(const float4*)(Bp + k0 + 4);
            bv2 = *(const float4*)(Bp + k0 + 8);
            bv3 = *(const float4*)(Bp + k0 + 12);
        }
#pragma unroll
        for (int k = 0; k < 32; k++) {
            float a0 = As[g][st][k][2 * ty];
            float a1 = As[g][st][k][2 * ty + 1];
            float4 bv = *(const float4*)(&Bs[g][st][k][tx * 4]);
            acc[0][0] = fmaf(a0, bv.x, acc[0][0]);
            acc[0][1] = fmaf(a0, bv.y, acc[0][1]);
            acc[0][2] = fmaf(a0, bv.z, acc[0][2]);
            acc[0][3] = fmaf(a0, bv.w, acc[0][3]);
            acc[1][0] = fmaf(a1, bv.x, acc[1][0]);
            acc[1][1] = fmaf(a1, bv.y, acc[1][1]);
            acc[1][2] = fmaf(a1, bv.z, acc[1][2]);
            acc[1][3] = fmaf(a1, bv.w, acc[1][3]);
        }
        // single barrier per iter is safe: 2-stage ping + next iter's barrier
    }

    // ---- cross-group reduction ----
    if (g == 1) {
#pragma unroll
        for (int r = 0; r < 2; r++)
#pragma unroll
            for (int j = 0; j < 4; j++) red[l][r * 4 + j] = acc[r][j];
    }
    __syncthreads();
    if (g != 0) return;
#pragma unroll
    for (int r = 0; r < 2; r++)
#pragma unroll
        for (int j = 0; j < 4; j++) acc[r][j] += red[l][r * 4 + j];

    const int m0 = bm + 2 * ty;
    const int n0 = bn + 4 * tx;
#pragma unroll
    for (int r = 0; r < 2; r++) {
        const int m = m0 + r;
        if (MODE == 2) {
            const int h = n0 >> 2;         // j' = 4h + gate
            float gi = acc[r][0] + g_bcat[n0];
            float gf = acc[r][1] + g_bcat[n0 + 1];
            float gg = acc[r][2] + g_bcat[n0 + 2];
            float go = acc[r][3] + g_bcat[n0 + 3];
            float c = sigmf(gf) * g_c[m * HDIM + h] + sigmf(gi) * tanhf(gg);
            float hn = sigmf(go) * tanhf(c);
            g_c[m * HDIM + h] = c;
            g_h[m * HDIM + h] = hn;
            g_z[m * ZROW + 512 + wr_par * 512 + h] = hn;
            float hi = tf32r(hn);
            float lo = tf32r(hn - hi);
            write_afrag(m, h, hi);
            write_afrag(m, h + 512, hi);
            write_afrag(m, h + 1024, lo);
            if (blockIdx.x == 0 && tx == 0) am_clr[m] = 0ull;
        } else {
#pragma unroll
            for (int j = 0; j < 4; j++) {
                const int n = n0 + j;
                float v = acc[r][j] + bias[n];
                if (MODE == 0) {
                    C[(size_t)m * N + n] = v;
                } else if (MODE == 1) {
                    float s = sigmf(v);
                    g_z[m * ZROW + n] = s * g_ctx[m * 512 + n];
                } else if (MODE == 4) {
                    C[(size_t)m * N + n] = v;
                    g_z[m * ZROW + 512 + n] = v;   // hn slot 0
                    float hi = tf32r(v);
                    float lo = tf32r(v - hi);
                    write_afrag(m, n, hi);
                    write_afrag(m, n + 512, hi);
                    write_afrag(m, n + 1024, lo);
                }
            }
        }
    }
}

// ---------------- small kernels ----------------
__global__ void k_mean(const float* __restrict__ feat) {
    int b = blockIdx.x, e = threadIdx.x;
    const float* f = feat + (size_t)b * PIX * EDIM + e;
    float s = 0.0f;
    for (int p = 0; p < PIX; p++) s += f[(size_t)p * EDIM];
    g_mean[b * EDIM + e] = s * (1.0f / (float)PIX);
}

// seed buffer 1 with the first caption token (gates_0 reads buffer 1)
__global__ void k_x0(const int* __restrict__ captions) {
    int b = threadIdx.x;
    g_amax2[1][b] = amax_key(0.0f, captions[b * TT]);
}

// repack [W_lih|W_lhh] -> row j' = 4h + gate; combined bias too
__global__ void k_pack(const float* __restrict__ Wlih, const float* __restrict__ Wlhh,
                       const float* __restrict__ blih, const float* __restrict__ blhh) {
    int i = blockIdx.x * blockDim.x + threadIdx.x;
    if (i >= G4 * KP) return;
    int jp = i / KP, k = i - jp * KP;
    int h = jp >> 2, gate = jp & 3;
    int orig = gate * 512 + h;
    g_Wcat[i] = (k < 1024) ? Wlih[(size_t)orig * 1024 + k]
                           : Wlhh[(size_t)orig * 512 + (k - 1024)];
    if (k == 0) g_bcat[jp] = blih[orig] + blhh[orig];
}

// per-batch attention (R4-proven): reads g_q, writes g_ctx
__global__ __launch_bounds__(512)
void k_att(const float* __restrict__ feat, const float* __restrict__ Watt,
           const float* __restrict__ batt) {
    __shared__ float q_s[ADIM];
    __shared__ float w_s[ADIM];
    __shared__ float e_s[PIX];
    __shared__ float red[16];
    const int b = blockIdx.x, tid = threadIdx.x;
    const int warp = tid >> 5, lane = tid & 31;

    q_s[tid] = g_q[b * ADIM + tid];
    w_s[tid] = Watt[tid];
    __syncthreads();

    for (int p = warp; p < PIX; p += 16) {
        const float* kap = g_ka + ((size_t)(b * PIX + p)) * ADIM;
        float s = 0.0f;
        for (int a = lane; a < ADIM; a += 32) {
            float v = kap[a] + q_s[a];
            s += fmaxf(v, 0.0f) * w_s[a];
        }
#pragma unroll
        for (int o = 16; o; o >>= 1) s += __shfl_xor_sync(0xffffffffu, s, o);
        if (lane == 0) e_s[p] = s + batt[0];
    }
    __syncthreads();

    float m = (tid < PIX) ? e_s[tid] : -3.4e38f;
#pragma unroll
    for (int o = 16; o; o >>= 1) m = fmaxf(m, __shfl_xor_sync(0xffffffffu, m, o));
    if (lane == 0) red[warp] = m;
    __syncthreads();
    if (tid == 0) {
        float v = red[0];
        for (int i = 1; i < 16; i++) v = fmaxf(v, red[i]);
        red[0] = v;
    }
    __syncthreads();
    m = red[0];
    float ex = (tid < PIX) ? expf(e_s[tid] - m) : 0.0f;
    float ssum = ex;
#pragma unroll
    for (int o = 16; o; o >>= 1) ssum += __shfl_xor_sync(0xffffffffu, ssum, o);
    __syncthreads();
    if (lane == 0) red[warp] = ssum;
    __syncthreads();
    if (tid == 0) {
        float v = 0.0f;
        for (int i = 0; i < 16; i++) v += red[i];
        red[0] = 1.0f / v;
    }
    __syncthreads();
    if (tid < PIX) e_s[tid] = ex * red[0];
    __syncthreads();

    float acc = 0.0f;
    const float* fb = feat + (size_t)b * PIX * EDIM + tid;
    for (int p = 0; p < PIX; p++) acc = fmaf(e_s[p], fb[(size_t)p * EDIM], acc);
    g_ctx[b * EDIM + tid] = acc;
}

// final transpose: scratch (b,t,v) -> out (b,v,t)
__global__ __launch_bounds__(256)
void k_tr(float* __restrict__ out) {
    __shared__ float sm[256 * 21];
    const int b = blockIdx.y;
    const int v0 = blockIdx.x * 256;
    const int tid = threadIdx.x;
    const float* src = g_scratch + (size_t)b * TT * VOC;
#pragma unroll
    for (int t = 0; t < TT; t++) sm[tid * 21 + t] = src[(size_t)t * VOC + v0 + tid];
    __syncthreads();
    float* ob = out + (size_t)b * VOC * TT + (size_t)v0 * TT;
    for (int e = tid; e < 256 * TT; e += 256) {
        int v = e / TT, t = e - v * TT;
        ob[e] = sm[v * 21 + t];
    }
}

// ---------------- host launch ----------------
static inline void* sym_addr(const void* symbol) {
    void* p = nullptr;
    cudaGetSymbolAddress(&p, symbol);
    return p;
}

extern "C" void kernel_launch(void* const* d_in, const int* in_sizes, int n_in,
                              void* d_out, int out_size) {
    const float* feat    = (const float*)d_in[0];
    const int*   caps    = (const int*)d_in[1];
    const float* W_ienc  = (const float*)d_in[2];
    const float* b_ienc  = (const float*)d_in[3];
    const float* W_oenc  = (const float*)d_in[4];
    const float* b_oenc  = (const float*)d_in[5];
    const float* W_att   = (const float*)d_in[6];
    const float* b_att   = (const float*)d_in[7];
    const float* W_inith = (const float*)d_in[8];
    const float* b_inith = (const float*)d_in[9];
    const float* W_initc = (const float*)d_in[10];
    const float* b_initc = (const float*)d_in[11];
    const float* W_gate  = (const float*)d_in[12];
    const float* b_gate  = (const float*)d_in[13];
    const float* embT    = (const float*)d_in[14];
    const float* W_lih   = (const float*)d_in[15];
    const float* W_lhh   = (const float*)d_in[16];
    const float* b_lih   = (const float*)d_in[17];
    const float* b_lhh   = (const float*)d_in[18];
    const float* W_out   = (const float*)d_in[19];
    const float* b_out   = (const float*)d_in[20];
    float* out = (float*)d_out;

    float* p_mean = (float*)sym_addr(g_mean);
    float* p_h    = (float*)sym_addr(g_h);
    float* p_c    = (float*)sym_addr(g_c);
    float* p_q    = (float*)sym_addr(g_q);
    float* p_ctx  = (float*)sym_addr(g_ctx);
    float* p_ka   = (float*)sym_addr(g_ka);
    unsigned long long* p_am = (unsigned long long*)sym_addr(g_amax2);  // [2][BSZ]

    static cudaStream_t s1 = nullptr;
    static cudaEvent_t evRoot, evK, evB;
    if (!s1) {
        cudaFuncSetAttribute(logits_mma, cudaFuncAttributeMaxDynamicSharedMemorySize, L_SMEM);
        cudaStreamCreateWithFlags(&s1, cudaStreamNonBlocking);
        cudaEventCreateWithFlags(&evRoot, cudaEventDisableTiming);
        cudaEventCreateWithFlags(&evK,    cudaEventDisableTiming);
        cudaEventCreateWithFlags(&evB,    cudaEventDisableTiming);
    }

    const dim3 gsQ(ADIM / 64, BSZ / 16);   // 8 x 8 = 64 blocks
    const dim3 gsG(G4 / 64, BSZ / 16);     // 32 x 8 = 256 blocks

    // ---- fork side stream: ka GEMM + B-fragment build ----
    cudaEventRecord(evRoot, 0);
    cudaStreamWaitEvent(s1, evRoot, 0);
    sgemm_nt<<<dim3(ADIM / 128, (BSZ * PIX) / 128), 256, 0, s1>>>(
        feat, W_ienc, b_ienc, p_ka, BSZ * PIX, ADIM, EDIM);
    cudaEventRecord(evK, s1);
    {
        size_t nB = (size_t)NTILES * NKS * 32;
        k_bfrag<<<(unsigned)((nB + 255) / 256), 256, 0, s1>>>(W_out);
    }
    cudaEventRecord(evB, s1);

    // ---- main-stream setup ----
    k_mean<<<BSZ, 512>>>(feat);
    gemm_ks<4><<<gsQ, 256>>>(p_mean, W_inith, b_inith, p_h, HDIM, EDIM,
                             nullptr, nullptr, nullptr, 0, 0);
    gemm_ks<0><<<gsQ, 256>>>(p_mean, W_initc, b_initc, p_c, HDIM, EDIM,
                             nullptr, nullptr, nullptr, 0, 0);
    k_x0<<<1, 128>>>(caps);
    k_pack<<<(G4 * KP + 255) / 256, 256>>>(W_lih, W_lhh, b_lih, b_lhh);

    cudaStreamWaitEvent(0, evK, 0);   // att needs ka
    cudaStreamWaitEvent(0, evB, 0);   // logits needs Bfrag; rejoins s1

    // ---- T recurrent steps (5 kernels each) ----
    for (int t = 0; t < TT; t++) {
        gemm_ks<0><<<gsQ, 256>>>(p_h, W_oenc, b_oenc, p_q, ADIM, HDIM,
                                 nullptr, nullptr, nullptr, 0, 0);
        k_att<<<BSZ, 512>>>(feat, W_att, b_att);
        gemm_ks<1><<<gsQ, 256>>>(p_ctx, W_gate, b_gate, nullptr, EDIM, EDIM,
                                 nullptr, nullptr, nullptr, 0, 0);
        gemm_ks<2><<<gsG, 256>>>(nullptr, (const float*)sym_addr(g_Wcat), nullptr,
                                 nullptr, G4, KP, embT,
                                 p_am + ((t + 1) & 1) * BSZ, p_am + (t & 1) * BSZ,
                                 t & 1, (t + 1) & 1);
        logits_mma<<<VOC / 128, 256, L_SMEM>>>(b_out, t);
    }

    k_tr<<<dim3(VOC / 256, BSZ), 256>>>(out);
}

// round 9
// speedup vs baseline: 1.4136x; 1.1882x over previous
#include <cuda_runtime.h>
#include <cuda_fp16.h>
#include <math.h>
#include <stdint.h>

// Problem constants
#define BSZ 128
#define PIX 196
#define EDIM 512
#define HDIM 512
#define ADIM 512
#define EMBD 512
#define VOC 32000
#define TT 20
#define ZROW 1536   // per-row: [ctx(512) | hn_slot0(512) | hn_slot1(512)]
#define G4 2048     // 4*H
#define KP 1536

// fp16 dual-split logits geometry: k16 steps
#define NKS_M 64                // mixed sweep: [hi|lo_s] x [lo_s|hi], K''=1024
#define NKS_H 32                // hihi sweep: K=512
#define NT8 (VOC / 8)           // 4000 n-tiles of 8

// ---------------- device scratch ----------------
__device__ float g_mean[BSZ * EDIM];
__device__ float g_h[BSZ * HDIM];
__device__ float g_c[BSZ * HDIM];
__device__ float g_q[BSZ * ADIM];
__device__ float g_ctx[BSZ * EDIM];
__device__ float g_z[BSZ * ZROW];                   // [ctx | hn0 | hn1]
__device__ float g_ka[BSZ * PIX * ADIM];            // 51.4 MB
__device__ float g_Wcat[G4 * KP];                   // repacked [j'=4h+gate][1536]
__device__ float g_bcat[G4];
__device__ float g_scratch[(size_t)BSZ * TT * VOC]; // 327 MB, (b,t,v)
__device__ unsigned long long g_amax2[2][BSZ];      // double-buffered argmax keys
// fp16 mma fragments: A (hn), B (W_out)
__device__ __half g_AfragM[8 * NKS_M * 32 * 8];            // 262 KB
__device__ __half g_AfragH[8 * NKS_H * 32 * 8];            // 131 KB
__device__ __half g_BfragM[(size_t)NT8 * NKS_M * 32 * 4];  // 65.5 MB
__device__ __half g_BfragH[(size_t)NT8 * NKS_H * 32 * 4];  // 32.8 MB

#define LO_SCALE 2048.0f
#define LO_INV   (1.0f / 2048.0f)

__device__ __forceinline__ float sigmf(float x) { return 1.0f / (1.0f + expf(-x)); }

__device__ __forceinline__ unsigned long long amax_key(float v, int n) {
    unsigned u = __float_as_uint(v);
    u = (u & 0x80000000u) ? ~u : (u | 0x80000000u);
    return ((unsigned long long)u << 32) | (unsigned long long)(0xFFFFFFFFu - (unsigned)n);
}
__device__ __forceinline__ int amax_idx(unsigned long long key) {
    return (int)(0xFFFFFFFFu - (unsigned)(key & 0xFFFFFFFFull));
}

// ---- fp16 m16n8k16 fragment element addressing (row.col) ----
// A (16x16): lane = 4*(row&7) + ((col&15)>>1 & 3); reg = (row&15>=8) + 2*(col&15>=8)
__device__ __forceinline__ void wrA16(__half* base, int nks, int m, int k, __half v) {
    const int mt = m >> 4, mr = m & 15;
    const int ks = k >> 4, kk = k & 15;
    const int lane = 4 * (mr & 7) + ((kk >> 1) & 3);
    const int reg = ((mr >= 8) ? 1 : 0) + ((kk >= 8) ? 2 : 0);
    base[(((size_t)mt * nks + ks) * 32 + lane) * 8 + reg * 2 + (kk & 1)] = v;
}
// B (16x8 col-major): lane = 4*(n&7) + ((k&15)>>1 & 3); reg = (k&15)>=8
__device__ __forceinline__ void wrB16(__half* base, int nks, int n, int k, __half v) {
    const int nt = n >> 3;
    const int ks = k >> 4, kk = k & 15;
    const int lane = 4 * (n & 7) + ((kk >> 1) & 3);
    const int reg = (kk >= 8) ? 1 : 0;
    base[(((size_t)nt * nks + ks) * 32 + lane) * 4 + reg * 2 + (kk & 1)] = v;
}

// write all three A-fragment images of one hn value
__device__ __forceinline__ void put_afrag(int m, int h, float v) {
    __half hi = __float2half(v);
    __half lo = __float2half((v - __half2float(hi)) * LO_SCALE);
    wrA16(g_AfragM, NKS_M, m, h, hi);          // mixed ks<32: hi
    wrA16(g_AfragM, NKS_M, m, 512 + h, lo);    // mixed ks>=32: lo_s
    wrA16(g_AfragH, NKS_H, m, h, hi);
}

// ---------------- cp.async / mma helpers ----------------
__device__ __forceinline__ uint32_t smem_u32(const void* p) {
    uint32_t a;
    asm("{ .reg .u64 t; cvta.to.shared.u64 t, %1; cvt.u32.u64 %0, t; }" : "=r"(a) : "l"(p));
    return a;
}
__device__ __forceinline__ void cp16(uint32_t s, const void* g) {
    asm volatile("cp.async.cg.shared.global [%0], [%1], 16;" :: "r"(s), "l"(g));
}
__device__ __forceinline__ void cp8(uint32_t s, const void* g) {
    asm volatile("cp.async.ca.shared.global [%0], [%1], 8;" :: "r"(s), "l"(g));
}
__device__ __forceinline__ void cp_commit() {
    asm volatile("cp.async.commit_group;" ::: "memory");
}
template <int N>
__device__ __forceinline__ void cp_wait() {
    asm volatile("cp.async.wait_group %0;" :: "n"(N) : "memory");
}

__device__ __forceinline__ void mma_f16(float& c0, float& c1, float& c2, float& c3,
                                        uint32_t a0, uint32_t a1, uint32_t a2, uint32_t a3,
                                        uint32_t b0, uint32_t b1) {
    asm volatile(
        "mma.sync.aligned.m16n8k16.row.col.f32.f16.f16.f32 "
        "{%0,%1,%2,%3}, {%4,%5,%6,%7}, {%8,%9}, {%0,%1,%2,%3};"
        : "+f"(c0), "+f"(c1), "+f"(c2), "+f"(c3)
        : "r"(a0), "r"(a1), "r"(a2), "r"(a3), "r"(b0), "r"(b1));
}

// ================= fp16 dual-split logits GEMM =================
// C[128,128/VOC-block] = hn @ W_out^T via two sweeps:
//   sweep M (64 k16-steps): (hi_a*lo_b + lo_a*hi_b) * 2^11  -> acc
//   acc *= 2^-11
//   sweep H (32 k16-steps): hi_a*hi_b                       -> acc
#define L_STAGE_B 32768
#define L_SMEM 69632

__global__ void __launch_bounds__(256, 2)
logits_mma(const float* __restrict__ bias, int t) {
    extern __shared__ char sm[];
    const uint32_t sb32 = smem_u32(sm);
    const int tid = threadIdx.x;
    const int wid = tid >> 5, lane = tid & 31;
    const int warpM = wid >> 2, warpN = wid & 3;
    const int nb0 = blockIdx.x * 16;
    const int n0 = blockIdx.x * 128;

    float c[4][4][4];
#pragma unroll
    for (int mi = 0; mi < 4; mi++)
#pragma unroll
        for (int ni = 0; ni < 4; ni++)
#pragma unroll
            for (int r = 0; r < 4; r++) c[mi][ni][r] = 0.0f;

    auto sweep = [&](const uint4* __restrict__ Af, const uint2* __restrict__ Bf,
                     int nks, int nchunk) {
        auto load_stage = [&](int cc) {
            const int ks0 = cc * 4;
            const uint32_t base = sb32 + (cc & 1) * L_STAGE_B;
#pragma unroll
            for (int i = 0; i < 4; i++) {          // A: 1024 x 16B
                const int idx = tid + i * 256;
                const int mt = idx >> 7, rem = idx & 127;
                const int ksl = rem >> 5, ln = rem & 31;
                cp16(base + idx * 16, Af + ((mt * nks + ks0 + ksl) * 32 + ln));
            }
#pragma unroll
            for (int i = 0; i < 8; i++) {          // B: 2048 x 8B
                const int idx = tid + i * 256;
                const int ntl = idx >> 7;
                const int ksl = (idx >> 5) & 3, ln = idx & 31;
                cp8(base + 16384 + idx * 8,
                    Bf + ((size_t)(nb0 + ntl) * nks + ks0 + ksl) * 32 + ln);
            }
            cp_commit();
        };

        load_stage(0);
        for (int cc = 0; cc < nchunk; cc++) {
            if (cc + 1 < nchunk) { load_stage(cc + 1); cp_wait<1>(); }
            else                 { cp_wait<0>(); }
            __syncthreads();
            const char* buf = sm + (cc & 1) * L_STAGE_B;
#pragma unroll
            for (int ksl = 0; ksl < 4; ksl++) {
                uint4 af[4];
                uint2 bf[4];
#pragma unroll
                for (int mi = 0; mi < 4; mi++) {
                    const int mt = warpM * 4 + mi;
                    af[mi] = *(const uint4*)(buf + ((mt * 4 + ksl) * 32 + lane) * 16);
                }
#pragma unroll
                for (int ni = 0; ni < 4; ni++) {
                    const int nt = warpN * 4 + ni;
                    bf[ni] = *(const uint2*)(buf + 16384 + ((nt * 4 + ksl) * 32 + lane) * 8);
                }
#pragma unroll
                for (int mi = 0; mi < 4; mi++)
#pragma unroll
                    for (int ni = 0; ni < 4; ni++)
                        mma_f16(c[mi][ni][0], c[mi][ni][1], c[mi][ni][2], c[mi][ni][3],
                                af[mi].x, af[mi].y, af[mi].z, af[mi].w,
                                bf[ni].x, bf[ni].y);
            }
            __syncthreads();
        }
    };

    sweep((const uint4*)g_AfragM, (const uint2*)g_BfragM, NKS_M, NKS_M / 4);
#pragma unroll
    for (int mi = 0; mi < 4; mi++)        // undo the 2^11 lo pre-scale (exact)
#pragma unroll
        for (int ni = 0; ni < 4; ni++)
#pragma unroll
            for (int r = 0; r < 4; r++) c[mi][ni][r] *= LO_INV;
    sweep((const uint4*)g_AfragH, (const uint2*)g_BfragH, NKS_H, NKS_H / 4);

    // ---- epilogue (D layout identical to tf32 path) ----
    float* st = (float*)sm;                         // 128 x 132
    const int g = lane >> 2, t4 = lane & 3;
#pragma unroll
    for (int mi = 0; mi < 4; mi++) {
        const int m = warpM * 64 + mi * 16 + g;
#pragma unroll
        for (int ni = 0; ni < 4; ni++) {
            const int col = warpN * 32 + ni * 8 + 2 * t4;
            st[m * 132 + col]           = c[mi][ni][0];
            st[m * 132 + col + 1]       = c[mi][ni][1];
            st[(m + 8) * 132 + col]     = c[mi][ni][2];
            st[(m + 8) * 132 + col + 1] = c[mi][ni][3];
        }
    }
    __syncthreads();

    {
        const int row = tid & 127;
        const int c0 = (tid >> 7) * 64;
        float bestv = -3.4e38f;
        int bestn = 0;
#pragma unroll 8
        for (int cc2 = 0; cc2 < 64; cc2++) {
            const int col = c0 + cc2;
            float v = st[row * 132 + col] + __ldg(&bias[n0 + col]);
            if (v > bestv) { bestv = v; bestn = n0 + col; }
        }
        atomicMax(&g_amax2[t & 1][row], amax_key(bestv, bestn));
    }
    for (int idx = tid; idx < 128 * 128; idx += 256) {
        const int m2 = idx >> 7, cc2 = idx & 127;
        g_scratch[((size_t)m2 * TT + t) * VOC + n0 + cc2] =
            st[m2 * 132 + cc2] + __ldg(&bias[n0 + cc2]);
    }
}

// build fp16 B fragments from W_out (once per launch); one thread per element
__global__ void k_bfrag16(const float* __restrict__ W) {
    size_t i = (size_t)blockIdx.x * 256 + threadIdx.x;
    if (i >= (size_t)VOC * 512) return;
    const int n = (int)(i >> 9);
    const int k = (int)(i & 511);
    float w = W[i];
    __half hi = __float2half(w);
    __half lo = __float2half((w - __half2float(hi)) * LO_SCALE);
    wrB16(g_BfragM, NKS_M, n, k, lo);          // mixed ks<32: lo_s (pairs A hi)
    wrB16(g_BfragM, NKS_M, n, 512 + k, hi);    // mixed ks>=32: hi (pairs A lo_s)
    wrB16(g_BfragH, NKS_H, n, k, hi);
}

// ================= big-tile fp32 SGEMM (ka only) ================
__global__ __launch_bounds__(256)
void sgemm_nt(const float* __restrict__ A, const float* __restrict__ B,
              const float* __restrict__ bias, float* __restrict__ C,
              int M, int N, int K) {
    __shared__ float As[8][128];
    __shared__ float Bs[8][128];
    const int bm = blockIdx.y * 128;
    const int bn = blockIdx.x * 128;
    const int tid = threadIdx.x;
    const int tx = tid & 15;
    const int ty = tid >> 4;
    const int lrow = tid >> 1;
    const int lcol = (tid & 1) << 2;

    const float* Ap = A + (size_t)(bm + lrow) * K + lcol;
    const float* Bp = B + (size_t)(bn + lrow) * K + lcol;

    float acc[8][8];
#pragma unroll
    for (int i = 0; i < 8; i++)
#pragma unroll
        for (int j = 0; j < 8; j++) acc[i][j] = 0.0f;

    for (int k0 = 0; k0 < K; k0 += 8) {
        float4 av = *reinterpret_cast<const float4*>(Ap + k0);
        float4 bv = *reinterpret_cast<const float4*>(Bp + k0);
        As[lcol + 0][lrow] = av.x; As[lcol + 1][lrow] = av.y;
        As[lcol + 2][lrow] = av.z; As[lcol + 3][lrow] = av.w;
        Bs[lcol + 0][lrow] = bv.x; Bs[lcol + 1][lrow] = bv.y;
        Bs[lcol + 2][lrow] = bv.z; Bs[lcol + 3][lrow] = bv.w;
        __syncthreads();
#pragma unroll
        for (int k = 0; k < 8; k++) {
            float4 a0 = *reinterpret_cast<const float4*>(&As[k][ty * 8]);
            float4 a1 = *reinterpret_cast<const float4*>(&As[k][ty * 8 + 4]);
            float4 b0 = *reinterpret_cast<const float4*>(&Bs[k][tx * 8]);
            float4 b1 = *reinterpret_cast<const float4*>(&Bs[k][tx * 8 + 4]);
            float am[8] = {a0.x, a0.y, a0.z, a0.w, a1.x, a1.y, a1.z, a1.w};
            float bb[8] = {b0.x, b0.y, b0.z, b0.w, b1.x, b1.y, b1.z, b1.w};
#pragma unroll
            for (int i = 0; i < 8; i++)
#pragma unroll
                for (int j = 0; j < 8; j++) acc[i][j] = fmaf(am[i], bb[j], acc[i][j]);
        }
        __syncthreads();
    }

    const int row0 = bm + ty * 8;
    const int col0 = bn + tx * 8;
#pragma unroll
    for (int i = 0; i < 8; i++) {
        const int mm = row0 + i;
#pragma unroll
        for (int j = 0; j < 8; j++) {
            const int n = col0 + j;
            C[(size_t)mm * N + n] = acc[i][j] + bias[n];
        }
    }
}

// ================= K-split small-M GEMM (256 threads, 2 K-groups) =================
// MODE 0: C = acc + bias                       (q, cn-init)
// MODE 1: g_z[m][n] = sigmoid(acc+bias)*g_ctx  (gated ctx)
// MODE 2: gates + fused LSTM cell (+emb gather, hn ping-pong, amax clear)
// MODE 4: init hn: C + g_z hn slot 0 + A-fragment writes
template <int MODE>
__global__ __launch_bounds__(256)
void gemm_ks(const float* __restrict__ A, const float* __restrict__ B,
             const float* __restrict__ bias, float* __restrict__ C,
             int N, int K,
             const float* __restrict__ emb,
             const unsigned long long* __restrict__ am_rd,
             unsigned long long* __restrict__ am_clr,
             int rd_par, int wr_par) {
    __shared__ float As[2][2][32][16];
    __shared__ float Bs[2][2][32][64];
    __shared__ float red[128][8];
    const int bn = blockIdx.x * 64;
    const int bm = blockIdx.y * 16;
    const int tid = threadIdx.x;
    const int l = tid & 127;
    const int g = tid >> 7;               // K-group
    const int tx = l & 15;
    const int ty = l >> 4;
    const int ar = l >> 3;
    const int ac = (l & 7) * 4;
    const int br = l >> 1;
    const int bc = (l & 1) * 16;
    const int arow = bm + ar;
    const int kbase = g * (K >> 1);

    size_t tokoff = 0;
    if (MODE == 2) tokoff = (size_t)amax_idx(am_rd[arow]) * EMBD;
    const int hn_rd = 512 + rd_par * 512;

    const float* Bp = B + (size_t)(bn + br) * K + kbase + bc;

    auto ldA4 = [&](int k0) -> float4 {
        const int kk = kbase + k0 + ac;
        if (MODE == 2) {
            const float* s;
            if (kk < 512)       s = emb + tokoff + kk;
            else if (kk < 1024) s = g_z + (size_t)arow * ZROW + (kk - 512);
            else                s = g_z + (size_t)arow * ZROW + hn_rd + (kk - 1024);
            return *(const float4*)s;
        }
        return *(const float4*)(A + (size_t)arow * K + kk);
    };

    float4 av = ldA4(0);
    float4 bv0 = *(const float4*)(Bp + 0);
    float4 bv1 = *(const float4*)(Bp + 4);
    float4 bv2 = *(const float4*)(Bp + 8);
    float4 bv3 = *(const float4*)(Bp + 12);

    float acc[2][4] = {};
    const int nk = K >> 6;
    for (int it = 0; it < nk; it++) {
        const int st = it & 1;
        As[g][st][ac + 0][ar] = av.x; As[g][st][ac + 1][ar] = av.y;
        As[g][st][ac + 2][ar] = av.z; As[g][st][ac + 3][ar] = av.w;
        Bs[g][st][bc +  0][br] = bv0.x; Bs[g][st][bc +  1][br] = bv0.y;
        Bs[g][st][bc +  2][br] = bv0.z; Bs[g][st][bc +  3][br] = bv0.w;
        Bs[g][st][bc +  4][br] = bv1.x; Bs[g][st][bc +  5][br] = bv1.y;
        Bs[g][st][bc +  6][br] = bv1.z; Bs[g][st][bc +  7][br] = bv1.w;
        Bs[g][st][bc +  8][br] = bv2.x; Bs[g][st][bc +  9][br] = bv2.y;
        Bs[g][st][bc + 10][br] = bv2.z; Bs[g][st][bc + 11][br] = bv2.w;
        Bs[g][st][bc + 12][br] = bv3.x; Bs[g][st][bc + 13][br] = bv3.y;
        Bs[g][st][bc + 14][br] = bv3.z; Bs[g][st][bc + 15][br] = bv3.w;
        __syncthreads();
        if (it + 1 < nk) {
            const int k0 = (it + 1) << 5;
            av = ldA4(k0);
            bv0 = *(const float4*)(Bp + k0);
            bv1 = *(const float4*)(Bp + k0 + 4);
            bv2 = *(const float4*)(Bp + k0 + 8);
            bv3 = *(const float4*)(Bp + k0 + 12);
        }
#pragma unroll
        for (int k = 0; k < 32; k++) {
            float a0 = As[g][st][k][2 * ty];
            float a1 = As[g][st][k][2 * ty + 1];
            float4 bv = *(const float4*)(&Bs[g][st][k][tx * 4]);
            acc[0][0] = fmaf(a0, bv.x, acc[0][0]);
            acc[0][1] = fmaf(a0, bv.y, acc[0][1]);
            acc[0][2] = fmaf(a0, bv.z, acc[0][2]);
            acc[0][3] = fmaf(a0, bv.w, acc[0][3]);
            acc[1][0] = fmaf(a1, bv.x, acc[1][0]);
            acc[1][1] = fmaf(a1, bv.y, acc[1][1]);
            acc[1][2] = fmaf(a1, bv.z, acc[1][2]);
            acc[1][3] = fmaf(a1, bv.w, acc[1][3]);
        }
    }

    // ---- cross-group reduction ----
    if (g == 1) {
#pragma unroll
        for (int r = 0; r < 2; r++)
#pragma unroll
            for (int j = 0; j < 4; j++) red[l][r * 4 + j] = acc[r][j];
    }
    __syncthreads();
    if (g != 0) return;
#pragma unroll
    for (int r = 0; r < 2; r++)
#pragma unroll
        for (int j = 0; j < 4; j++) acc[r][j] += red[l][r * 4 + j];

    const int m0 = bm + 2 * ty;
    const int n0 = bn + 4 * tx;
#pragma unroll
    for (int r = 0; r < 2; r++) {
        const int m = m0 + r;
        if (MODE == 2) {
            const int h = n0 >> 2;
            float gi = acc[r][0] + g_bcat[n0];
            float gf = acc[r][1] + g_bcat[n0 + 1];
            float gg = acc[r][2] + g_bcat[n0 + 2];
            float go = acc[r][3] + g_bcat[n0 + 3];
            float c = sigmf(gf) * g_c[m * HDIM + h] + sigmf(gi) * tanhf(gg);
            float hn = sigmf(go) * tanhf(c);
            g_c[m * HDIM + h] = c;
            g_h[m * HDIM + h] = hn;
            g_z[m * ZROW + 512 + wr_par * 512 + h] = hn;
            put_afrag(m, h, hn);
            if (blockIdx.x == 0 && tx == 0) am_clr[m] = 0ull;
        } else {
#pragma unroll
            for (int j = 0; j < 4; j++) {
                const int n = n0 + j;
                float v = acc[r][j] + bias[n];
                if (MODE == 0) {
                    C[(size_t)m * N + n] = v;
                } else if (MODE == 1) {
                    float s = sigmf(v);
                    g_z[m * ZROW + n] = s * g_ctx[m * 512 + n];
                } else if (MODE == 4) {
                    C[(size_t)m * N + n] = v;
                    g_z[m * ZROW + 512 + n] = v;
                    put_afrag(m, n, v);
                }
            }
        }
    }
}

// ---------------- small kernels ----------------
__global__ void k_mean(const float* __restrict__ feat) {
    int b = blockIdx.x, e = threadIdx.x;
    const float* f = feat + (size_t)b * PIX * EDIM + e;
    float s = 0.0f;
    for (int p = 0; p < PIX; p++) s += f[(size_t)p * EDIM];
    g_mean[b * EDIM + e] = s * (1.0f / (float)PIX);
}

__global__ void k_x0(const int* __restrict__ captions) {
    int b = threadIdx.x;
    g_amax2[1][b] = amax_key(0.0f, captions[b * TT]);
}

__global__ void k_pack(const float* __restrict__ Wlih, const float* __restrict__ Wlhh,
                       const float* __restrict__ blih, const float* __restrict__ blhh) {
    int i = blockIdx.x * blockDim.x + threadIdx.x;
    if (i >= G4 * KP) return;
    int jp = i / KP, k = i - jp * KP;
    int h = jp >> 2, gate = jp & 3;
    int orig = gate * 512 + h;
    g_Wcat[i] = (k < 1024) ? Wlih[(size_t)orig * 1024 + k]
                           : Wlhh[(size_t)orig * 512 + (k - 1024)];
    if (k == 0) g_bcat[jp] = blih[orig] + blhh[orig];
}

__global__ __launch_bounds__(512)
void k_att(const float* __restrict__ feat, const float* __restrict__ Watt,
           const float* __restrict__ batt) {
    __shared__ float q_s[ADIM];
    __shared__ float w_s[ADIM];
    __shared__ float e_s[PIX];
    __shared__ float red[16];
    const int b = blockIdx.x, tid = threadIdx.x;
    const int warp = tid >> 5, lane = tid & 31;

    q_s[tid] = g_q[b * ADIM + tid];
    w_s[tid] = Watt[tid];
    __syncthreads();

    for (int p = warp; p < PIX; p += 16) {
        const float* kap = g_ka + ((size_t)(b * PIX + p)) * ADIM;
        float s = 0.0f;
        for (int a = lane; a < ADIM; a += 32) {
            float v = kap[a] + q_s[a];
            s += fmaxf(v, 0.0f) * w_s[a];
        }
#pragma unroll
        for (int o = 16; o; o >>= 1) s += __shfl_xor_sync(0xffffffffu, s, o);
        if (lane == 0) e_s[p] = s + batt[0];
    }
    __syncthreads();

    float m = (tid < PIX) ? e_s[tid] : -3.4e38f;
#pragma unroll
    for (int o = 16; o; o >>= 1) m = fmaxf(m, __shfl_xor_sync(0xffffffffu, m, o));
    if (lane == 0) red[warp] = m;
    __syncthreads();
    if (tid == 0) {
        float v = red[0];
        for (int i = 1; i < 16; i++) v = fmaxf(v, red[i]);
        red[0] = v;
    }
    __syncthreads();
    m = red[0];
    float ex = (tid < PIX) ? expf(e_s[tid] - m) : 0.0f;
    float ssum = ex;
#pragma unroll
    for (int o = 16; o; o >>= 1) ssum += __shfl_xor_sync(0xffffffffu, ssum, o);
    __syncthreads();
    if (lane == 0) red[warp] = ssum;
    __syncthreads();
    if (tid == 0) {
        float v = 0.0f;
        for (int i = 0; i < 16; i++) v += red[i];
        red[0] = 1.0f / v;
    }
    __syncthreads();
    if (tid < PIX) e_s[tid] = ex * red[0];
    __syncthreads();

    float acc = 0.0f;
    const float* fb = feat + (size_t)b * PIX * EDIM + tid;
    for (int p = 0; p < PIX; p++) acc = fmaf(e_s[p], fb[(size_t)p * EDIM], acc);
    g_ctx[b * EDIM + tid] = acc;
}

__global__ __launch_bounds__(256)
void k_tr(float* __restrict__ out) {
    __shared__ float sm[256 * 21];
    const int b = blockIdx.y;
    const int v0 = blockIdx.x * 256;
    const int tid = threadIdx.x;
    const float* src = g_scratch + (size_t)b * TT * VOC;
#pragma unroll
    for (int t = 0; t < TT; t++) sm[tid * 21 + t] = src[(size_t)t * VOC + v0 + tid];
    __syncthreads();
    float* ob = out + (size_t)b * VOC * TT + (size_t)v0 * TT;
    for (int e = tid; e < 256 * TT; e += 256) {
        int v = e / TT, t = e - v * TT;
        ob[e] = sm[v * 21 + t];
    }
}

// ---------------- host launch ----------------
static inline void* sym_addr(const void* symbol) {
    void* p = nullptr;
    cudaGetSymbolAddress(&p, symbol);
    return p;
}

extern "C" void kernel_launch(void* const* d_in, const int* in_sizes, int n_in,
                              void* d_out, int out_size) {
    const float* feat    = (const float*)d_in[0];
    const int*   caps    = (const int*)d_in[1];
    const float* W_ienc  = (const float*)d_in[2];
    const float* b_ienc  = (const float*)d_in[3];
    const float* W_oenc  = (const float*)d_in[4];
    const float* b_oenc  = (const float*)d_in[5];
    const float* W_att   = (const float*)d_in[6];
    const float* b_att   = (const float*)d_in[7];
    const float* W_inith = (const float*)d_in[8];
    const float* b_inith = (const float*)d_in[9];
    const float* W_initc = (const float*)d_in[10];
    const float* b_initc = (const float*)d_in[11];
    const float* W_gate  = (const float*)d_in[12];
    const float* b_gate  = (const float*)d_in[13];
    const float* embT    = (const float*)d_in[14];
    const float* W_lih   = (const float*)d_in[15];
    const float* W_lhh   = (const float*)d_in[16];
    const float* b_lih   = (const float*)d_in[17];
    const float* b_lhh   = (const float*)d_in[18];
    const float* W_out   = (const float*)d_in[19];
    const float* b_out   = (const float*)d_in[20];
    float* out = (float*)d_out;

    float* p_mean = (float*)sym_addr(g_mean);
    float* p_h    = (float*)sym_addr(g_h);
    float* p_c    = (float*)sym_addr(g_c);
    float* p_q    = (float*)sym_addr(g_q);
    float* p_ctx  = (float*)sym_addr(g_ctx);
    float* p_ka   = (float*)sym_addr(g_ka);
    float* p_Wcat = (float*)sym_addr(g_Wcat);
    unsigned long long* p_am = (unsigned long long*)sym_addr(g_amax2);

    static cudaStream_t s1 = nullptr;
    static cudaEvent_t evRoot, evK, evB;
    if (!s1) {
        cudaFuncSetAttribute(logits_mma, cudaFuncAttributeMaxDynamicSharedMemorySize, L_SMEM);
        cudaStreamCreateWithFlags(&s1, cudaStreamNonBlocking);
        cudaEventCreateWithFlags(&evRoot, cudaEventDisableTiming);
        cudaEventCreateWithFlags(&evK,    cudaEventDisableTiming);
        cudaEventCreateWithFlags(&evB,    cudaEventDisableTiming);
    }

    const dim3 gsQ(ADIM / 64, BSZ / 16);   // 64 blocks
    const dim3 gsG(G4 / 64, BSZ / 16);     // 256 blocks

    // ---- fork side stream: ka GEMM + fp16 B-fragment build ----
    cudaEventRecord(evRoot, 0);
    cudaStreamWaitEvent(s1, evRoot, 0);
    sgemm_nt<<<dim3(ADIM / 128, (BSZ * PIX) / 128), 256, 0, s1>>>(
        feat, W_ienc, b_ienc, p_ka, BSZ * PIX, ADIM, EDIM);
    cudaEventRecord(evK, s1);
    {
        size_t nE = (size_t)VOC * 512;
        k_bfrag16<<<(unsigned)((nE + 255) / 256), 256, 0, s1>>>(W_out);
    }
    cudaEventRecord(evB, s1);

    // ---- main-stream setup ----
    k_mean<<<BSZ, 512>>>(feat);
    gemm_ks<4><<<gsQ, 256>>>(p_mean, W_inith, b_inith, p_h, HDIM, EDIM,
                             nullptr, nullptr, nullptr, 0, 0);
    gemm_ks<0><<<gsQ, 256>>>(p_mean, W_initc, b_initc, p_c, HDIM, EDIM,
                             nullptr, nullptr, nullptr, 0, 0);
    k_x0<<<1, 128>>>(caps);
    k_pack<<<(G4 * KP + 255) / 256, 256>>>(W_lih, W_lhh, b_lih, b_lhh);

    cudaStreamWaitEvent(0, evK, 0);   // att needs ka
    cudaStreamWaitEvent(0, evB, 0);   // logits needs B fragments; rejoins s1

    // ---- T recurrent steps ----
    for (int t = 0; t < TT; t++) {
        gemm_ks<0><<<gsQ, 256>>>(p_h, W_oenc, b_oenc, p_q, ADIM, HDIM,
                                 nullptr, nullptr, nullptr, 0, 0);
        k_att<<<BSZ, 512>>>(feat, W_att, b_att);
        gemm_ks<1><<<gsQ, 256>>>(p_ctx, W_gate, b_gate, nullptr, EDIM, EDIM,
                                 nullptr, nullptr, nullptr, 0, 0);
        gemm_ks<2><<<gsG, 256>>>(nullptr, p_Wcat, nullptr, nullptr, G4, KP, embT,
                                 p_am + ((t + 1) & 1) * BSZ, p_am + (t & 1) * BSZ,
                                 t & 1, (t + 1) & 1);
        logits_mma<<<VOC / 128, 256, L_SMEM>>>(b_out, t);
    }

    k_tr<<<dim3(VOC / 256, BSZ), 256>>>(out);
}